// round 10
// baseline (speedup 1.0000x reference)
#include <cuda_runtime.h>
#include <cuda_fp16.h>
#include <math.h>
#include <stdint.h>

#define Bb 8
#define Nn 2048
#define Ff 64
#define MTILE 32
#define JT 64
#define NSTEPS (Nn / JT)        // 32

typedef unsigned long long ull;

// Scratch (device globals)
__device__ __half g_WhT[Bb * Ff * Nn];    // 2 MB f16  [b][f][j]
__device__ float4 g_e1pack[Bb * Nn];      // (e1, exp(e1), exp(0.2 e1), 0)
__device__ float4 g_e2pack[Bb * Nn];      // (e2, exp(e2), exp(0.2 e2), 0)
__device__ ull    g_adjmask[Nn * (Nn / 64)];   // 512 KB bitmask, bit j%64 of word [i][j/64]

// ------------------------- helpers ----------------------------
__device__ __forceinline__ uint32_t smem_u32(const void* p) {
    uint32_t a;
    asm("{ .reg .u64 t; cvta.to.shared.u64 t, %1; cvt.u32.u64 %0, t; }" : "=r"(a) : "l"(p));
    return a;
}
__device__ __forceinline__ uint32_t swz128(uint32_t off) {
    return off ^ ((off >> 3) & 0x70);
}
__device__ __forceinline__ void ldsm_x4(uint32_t& r0, uint32_t& r1, uint32_t& r2, uint32_t& r3,
                                        uint32_t addr) {
    asm volatile("ldmatrix.sync.aligned.m8n8.x4.shared.b16 {%0,%1,%2,%3}, [%4];"
                 : "=r"(r0), "=r"(r1), "=r"(r2), "=r"(r3) : "r"(addr));
}
__device__ __forceinline__ void ldsm_x2(uint32_t& r0, uint32_t& r1, uint32_t addr) {
    asm volatile("ldmatrix.sync.aligned.m8n8.x2.shared.b16 {%0,%1}, [%2];"
                 : "=r"(r0), "=r"(r1) : "r"(addr));
}
__device__ __forceinline__ void mma16816(float* c, const uint32_t* a, const uint32_t* bf) {
    asm volatile(
        "mma.sync.aligned.m16n8k16.row.col.f32.f16.f16.f32 "
        "{%0,%1,%2,%3}, {%4,%5,%6,%7}, {%8,%9}, {%0,%1,%2,%3};"
        : "+f"(c[0]), "+f"(c[1]), "+f"(c[2]), "+f"(c[3])
        : "r"(a[0]), "r"(a[1]), "r"(a[2]), "r"(a[3]), "r"(bf[0]), "r"(bf[1]));
}

// ---------------------------------------------------------------------------
// Kernel 1: Wh = h @ W^T, write WhT f16 directly (fused transpose),
// plus e1/e2 packs with precomputed exps.
// 256 CTAs x 256 thr; 32 rows/CTA; thread = (2 rows, 4 outs).
// ---------------------------------------------------------------------------
__global__ __launch_bounds__(256) void prep_kernel(const float* __restrict__ h,
                                                   const float* __restrict__ W,
                                                   const float* __restrict__ a)
{
    __shared__ __align__(16) float W_s[64][64];    // [f][o]
    __shared__ __align__(16) float h_s[32][64];
    __shared__ float red1[32][16];
    __shared__ float red2[32][16];
    __shared__ __align__(16) __half tT[64][40];    // [o][r], stride 80B (16B-aligned rows)

    const int t = threadIdx.x;
    const int row0 = blockIdx.x * 32;              // global row in [0, 16384)

    for (int idx = t; idx < 64 * 64; idx += 256) {
        int o = idx >> 6, f = idx & 63;
        W_s[f][o] = W[idx];                        // W is [o][f]
    }
    {
        const float4* hg = (const float4*)(h + (size_t)row0 * 64);
        float4* hs = (float4*)&h_s[0][0];
        hs[t]       = hg[t];
        hs[t + 256] = hg[t + 256];
    }
    __syncthreads();

    const int r0 = (t >> 4) * 2;
    const int o0 = (t & 15) << 2;
    float a0x=0.f,a0y=0.f,a0z=0.f,a0w=0.f;
    float a1x=0.f,a1y=0.f,a1z=0.f,a1w=0.f;
#pragma unroll
    for (int f = 0; f < 64; f++) {
        float4 w4 = *(const float4*)&W_s[f][o0];
        float h0 = h_s[r0][f], h1 = h_s[r0 + 1][f];
        a0x += h0 * w4.x; a0y += h0 * w4.y; a0z += h0 * w4.z; a0w += h0 * w4.w;
        a1x += h1 * w4.x; a1y += h1 * w4.y; a1z += h1 * w4.z; a1w += h1 * w4.w;
    }

    // transpose tile (f16)
    tT[o0 + 0][r0] = __float2half_rn(a0x); tT[o0 + 0][r0 + 1] = __float2half_rn(a1x);
    tT[o0 + 1][r0] = __float2half_rn(a0y); tT[o0 + 1][r0 + 1] = __float2half_rn(a1y);
    tT[o0 + 2][r0] = __float2half_rn(a0z); tT[o0 + 2][r0 + 1] = __float2half_rn(a1z);
    tT[o0 + 3][r0] = __float2half_rn(a0w); tT[o0 + 3][r0 + 1] = __float2half_rn(a1w);

    // e1/e2 partials
    float4 av1 = *(const float4*)&a[o0];
    float4 av2 = *(const float4*)&a[64 + o0];
    red1[r0][t & 15]     = a0x*av1.x + a0y*av1.y + a0z*av1.z + a0w*av1.w;
    red1[r0 + 1][t & 15] = a1x*av1.x + a1y*av1.y + a1z*av1.z + a1w*av1.w;
    red2[r0][t & 15]     = a0x*av2.x + a0y*av2.y + a0z*av2.z + a0w*av2.w;
    red2[r0 + 1][t & 15] = a1x*av2.x + a1y*av2.y + a1z*av2.z + a1w*av2.w;
    __syncthreads();

    if (t < 32) {
        float s1 = 0.f, s2 = 0.f;
#pragma unroll
        for (int k = 0; k < 16; k++) { s1 += red1[t][k]; s2 += red2[t][k]; }
        g_e1pack[row0 + t] = make_float4(s1, __expf(s1), __expf(0.2f * s1), 0.f);
        g_e2pack[row0 + t] = make_float4(s2, __expf(s2), __expf(0.2f * s2), 0.f);
    }

    // write WhT: thread t -> o = t>>2, 8 r's
    {
        const int b  = row0 / Nn;
        const int i0 = row0 % Nn;
        const int o  = t >> 2;
        const int rr = (t & 3) * 8;
        *(uint4*)(g_WhT + ((size_t)b * Ff + o) * Nn + i0 + rr) = *(const uint4*)&tT[o][rr];
    }
}

// ---------------------------------------------------------------------------
// Kernel 1b: pack adj>0 into bitmask. warp per row; 64 ballots per row.
// ---------------------------------------------------------------------------
__global__ __launch_bounds__(256) void bitpack_kernel(const float* __restrict__ adj)
{
    const int lane = threadIdx.x & 31;
    const int row  = (blockIdx.x * 256 + threadIdx.x) >> 5;    // 2048 rows
    uint32_t* mw = (uint32_t*)g_adjmask;
    const float* arow = adj + (size_t)row * Nn;
#pragma unroll 4
    for (int w = 0; w < 64; w++) {
        float av = __ldg(&arow[w * 32 + lane]);
        uint32_t m = __ballot_sync(0xffffffffu, av > 0.f);
        if (lane == 0) mw[row * 64 + w] = m;
    }
}

// ---------------------------------------------------------------------------
// Kernel 2: fused GAT via HMMA. CTA = 256 thr (8 warps), tile 32 i x 64 f.
// p-gen: NO exp in loop (factored exps), NO adj floats (bitmask broadcast).
// Warp tile 16i x 16f (wm=wid&1, wn=wid>>1). grid (64, 8) = 512 CTAs.
// ---------------------------------------------------------------------------
__global__ __launch_bounds__(256, 4) void gat_hmma(float* __restrict__ out)
{
    __shared__ __align__(128) __half A_s[MTILE * 64];   // 4 KB, row = i, 128B
    __shared__ __align__(128) __half B_s[64 * 64];      // 8 KB, row = f, 128B
    __shared__ float e1_s[MTILE], E1p_s[MTILE], E1n_s[MTILE];
    __shared__ float Z_s[MTILE];

    const int t    = threadIdx.x;
    const int lane = t & 31;
    const int wid  = t >> 5;
    const int wm   = wid & 1;     // rows wm*16 .. +15
    const int wn   = wid >> 1;    // cols wn*16 .. +15
    const int i0   = blockIdx.x * MTILE;
    const int b    = blockIdx.y;

    if (t < MTILE) {
        float4 p = g_e1pack[(size_t)b * Nn + i0 + t];
        e1_s[t] = p.x; E1p_s[t] = p.y; E1n_s[t] = p.z;
    }

    const uint32_t Abase = smem_u32(A_s);
    const uint32_t Bbase = smem_u32(B_s);

    const uint32_t xv = (lane & 7) << 4;
    const uint32_t aRowOff = (uint32_t)(wm * 16 + (lane & 7) + ((lane >> 3) & 1) * 8) * 128;
    const uint32_t akbo    = ((lane >> 4) & 1) * 16;
    const uint32_t bRowOff = (uint32_t)(wn * 16 + (lane & 7)) * 128;
    const uint32_t bkbo    = ((lane >> 3) & 1) * 16;

    float acc[2][4];
#pragma unroll
    for (int nf = 0; nf < 2; nf++)
#pragma unroll
        for (int c = 0; c < 4; c++) acc[nf][c] = 0.f;

    float zpart[4] = {0.f, 0.f, 0.f, 0.f};

    const float4* e2p = g_e2pack + (size_t)b * Nn;

    for (int s = 0; s < NSTEPS; s++) {
        const int j0 = s * JT;
        __syncthreads();    // previous tiles consumed

        // stage B tile: 64 f-rows x 128B
        {
#pragma unroll
            for (int it = 0; it < 2; it++) {
                int idx = t + it * 256;
                int f = idx >> 3, c = idx & 7;
                uint4 v = *(const uint4*)(g_WhT + ((size_t)b * Ff + f) * Nn + j0 + c * 8);
                *(uint4*)((char*)B_s + swz128(f * 128 + c * 16)) = v;
            }
        }
        // p-gen: warp wid -> rows wid*4 .. +3; lane -> j pair
        {
            float4 jp0 = __ldg(&e2p[j0 + 2 * lane]);
            float4 jp1 = __ldg(&e2p[j0 + 2 * lane + 1]);
#pragma unroll
            for (int g = 0; g < 4; g++) {
                int i = wid * 4 + g;
                ull m = __ldg(&g_adjmask[(size_t)(i0 + i) * (Nn / 64) + s]);
                float e1v = e1_s[i], e1pv = E1p_s[i], e1nv = E1n_s[i];
                float p0 = (e1v + jp0.x > 0.f) ? e1pv * jp0.y : e1nv * jp0.z;
                float p1 = (e1v + jp1.x > 0.f) ? e1pv * jp1.y : e1nv * jp1.z;
                p0 = ((m >> (2 * lane)) & 1ull)     ? p0 : 0.f;
                p1 = ((m >> (2 * lane + 1)) & 1ull) ? p1 : 0.f;
                __half2 ph = __floats2half2_rn(p0, p1);
                float2 pf = __half22float2(ph);          // rounded: matches numerator
                zpart[g] += pf.x + pf.y;
                *(__half2*)((char*)A_s + swz128(i * 128 + lane * 4)) = ph;
            }
        }
        __syncthreads();

        // HMMA: 4 k-frags x (1 ldsm.x4 + 2 ldsm.x2 + 2 mma)
#pragma unroll
        for (int kf = 0; kf < 4; kf++) {
            const uint32_t kb = kf * 32;
            uint32_t a4[4];
            ldsm_x4(a4[0], a4[1], a4[2], a4[3], Abase + aRowOff + ((kb + akbo) ^ xv));
#pragma unroll
            for (int nf = 0; nf < 2; nf++) {
                uint32_t bf[2];
                ldsm_x2(bf[0], bf[1], Bbase + bRowOff + nf * 1024 + ((kb + bkbo) ^ xv));
                mma16816(acc[nf], a4, bf);
            }
        }
    }

    // reduce Z (warp wid owns rows wid*4..+3)
#pragma unroll
    for (int g = 0; g < 4; g++) {
        float z = zpart[g];
#pragma unroll
        for (int off = 16; off; off >>= 1)
            z += __shfl_xor_sync(0xffffffffu, z, off);
        if (lane == 0) Z_s[wid * 4 + g] = z;
    }
    __syncthreads();

    // epilogue
    {
        const int r_lo = wm * 16 + (lane >> 2);
        const int r_hi = r_lo + 8;
        const float zlo = 1.0f / Z_s[r_lo];
        const float zhi = 1.0f / Z_s[r_hi];
        float* olo = out + ((size_t)b * Nn + i0 + r_lo) * 64;
        float* ohi = out + ((size_t)b * Nn + i0 + r_hi) * 64;
#pragma unroll
        for (int nf = 0; nf < 2; nf++) {
            const int col = wn * 16 + nf * 8 + 2 * (lane & 3);
            float2 v;
            v.x = acc[nf][0] * zlo; v.y = acc[nf][1] * zlo;
            v.x = v.x > 0.f ? v.x : expm1f(v.x);
            v.y = v.y > 0.f ? v.y : expm1f(v.y);
            *(float2*)(olo + col) = v;
            v.x = acc[nf][2] * zhi; v.y = acc[nf][3] * zhi;
            v.x = v.x > 0.f ? v.x : expm1f(v.x);
            v.y = v.y > 0.f ? v.y : expm1f(v.y);
            *(float2*)(ohi + col) = v;
        }
    }
}

// ---------------------------------------------------------------------------
extern "C" void kernel_launch(void* const* d_in, const int* in_sizes, int n_in,
                              void* d_out, int out_size)
{
    const float* h = nullptr; const float* adj = nullptr;
    const float* W = nullptr; const float* a = nullptr;
    for (int i = 0; i < n_in; i++) {
        switch (in_sizes[i]) {
            case Bb * Nn * Ff: h   = (const float*)d_in[i]; break;
            case Nn * Nn:      adj = (const float*)d_in[i]; break;
            case Ff * Ff:      W   = (const float*)d_in[i]; break;
            case 2 * Ff:       a   = (const float*)d_in[i]; break;
            default: break;
        }
    }
    (void)out_size;

    prep_kernel<<<(Bb * Nn) / 32, 256>>>(h, W, a);
    bitpack_kernel<<<Nn / 8, 256>>>(adj);
    gat_hmma<<<dim3(Nn / MTILE, Bb), 256>>>((float*)d_out);
}